// round 15
// baseline (speedup 1.0000x reference)
#include <cuda_runtime.h>
#include <cuda_fp16.h>
#include <cstdint>
#include <cstddef>

#define N_NODES 100000
#define N_EDGES 600000
#define DMODEL  128
#define NREL    50
#define N_PAD   100096          // 782 tiles * 128

// Scratch
__device__ float  g_G[4 * N_NODES];                     // gate pre-activations
__device__ __half g_Hh[(size_t)4 * N_PAD * DMODEL];     // aggregated gated inputs (fp16)
__device__ __half g_Wh4[4 * 128 * 136];                 // fp16 weights, padded pitch 136
// CSR-by-target scratch
__device__ int g_cnt[N_NODES];
__device__ int g_fill[N_NODES];
__device__ int g_start[N_NODES];
__device__ int g_perm[N_EDGES];
__device__ int g_cursor[1];

#define MMA_F16(c, a0, a1, a2, a3, b0, b1)                                   \
    asm volatile("mma.sync.aligned.m16n8k16.row.col.f32.f16.f16.f32 "        \
                 "{%0,%1,%2,%3}, {%4,%5,%6,%7}, {%8,%9}, {%0,%1,%2,%3};"     \
                 : "+f"(c[0]), "+f"(c[1]), "+f"(c[2]), "+f"(c[3])            \
                 : "r"(a0), "r"(a1), "r"(a2), "r"(a3), "r"(b0), "r"(b1))

__device__ __forceinline__ uint32_t smem_u32(const void* p) {
    uint32_t a;
    asm("{ .reg .u64 t; cvta.to.shared.u64 t, %1; cvt.u32.u64 %0, t; }" : "=r"(a) : "l"(p));
    return a;
}
__device__ __forceinline__ void cpa16(uint32_t dst, const void* src) {
    asm volatile("cp.async.cg.shared.global [%0], [%1], 16;" :: "r"(dst), "l"(src));
}
#define CPA_COMMIT() asm volatile("cp.async.commit_group;" ::: "memory")
#define CPA_WAIT0()  asm volatile("cp.async.wait_group 0;" ::: "memory")

// ---- CSR build ----
__global__ __launch_bounds__(256) void zero_kernel() {
    int i = blockIdx.x * 256 + threadIdx.x;
    if (i < N_NODES) { g_cnt[i] = 0; g_fill[i] = 0; }
    if (i == 0) g_cursor[0] = 0;
}

__global__ __launch_bounds__(256) void hist_kernel(const int* __restrict__ eidx) {
    int e = blockIdx.x * 256 + threadIdx.x;
    if (e < N_EDGES) atomicAdd(&g_cnt[eidx[N_EDGES + e]], 1);
}

__global__ __launch_bounds__(256) void alloc_kernel() {
    int n = blockIdx.x * 256 + threadIdx.x;
    int lane = threadIdx.x & 31, warp = threadIdx.x >> 5;
    int c = (n < N_NODES) ? g_cnt[n] : 0;
    int incl = c;
    #pragma unroll
    for (int off = 1; off < 32; off <<= 1) {
        int y = __shfl_up_sync(0xffffffff, incl, off);
        if (lane >= off) incl += y;
    }
    __shared__ int wsum[8], wbase[8], bbase;
    if (lane == 31) wsum[warp] = incl;
    __syncthreads();
    if (threadIdx.x == 0) {
        int s = 0;
        #pragma unroll
        for (int w = 0; w < 8; w++) { wbase[w] = s; s += wsum[w]; }
        bbase = atomicAdd(&g_cursor[0], s);
    }
    __syncthreads();
    if (n < N_NODES) g_start[n] = bbase + wbase[warp] + (incl - c);
}

__global__ __launch_bounds__(256) void scatter_kernel(const int* __restrict__ eidx) {
    int e = blockIdx.x * 256 + threadIdx.x;
    if (e < N_EDGES) {
        int tgt = eidx[N_EDGES + e];
        int pos = g_start[tgt] + atomicAdd(&g_fill[tgt], 1);
        g_perm[pos] = e;
    }
}

// ---- weights -> fp16, padded pitch-136 layout ----
__global__ __launch_bounds__(256) void prep_weights_kernel(
    const float* __restrict__ W0, const float* __restrict__ W1,
    const float* __restrict__ W2, const float* __restrict__ W3)
{
    for (int e = blockIdx.x * 256 + threadIdx.x; e < 4 * 128 * 64; e += gridDim.x * 256) {
        int t = e >> 13, r = (e >> 6) & 127, cp = e & 63;
        const float* W = (t == 0) ? W0 : (t == 1) ? W1 : (t == 2) ? W2 : W3;
        float2 v = reinterpret_cast<const float2*>(W)[r * 64 + cp];
        __half2 h = __float22half2_rn(v);
        *reinterpret_cast<__half2*>(&g_Wh4[t * 128 * 136 + r * 136 + 2 * cp]) = h;
    }
}

// ---- gate pre-activations (fp32 GEMV); also warms L2 with inp ----
__global__ __launch_bounds__(256) void gate_kernel(
    const float* __restrict__ inp,
    const float* __restrict__ G0, const float* __restrict__ G1,
    const float* __restrict__ G2, const float* __restrict__ G3)
{
    int warp = threadIdx.x >> 5, lane = threadIdx.x & 31;
    int row = blockIdx.x * 8 + warp;
    if (row >= N_NODES) return;

    float4 v  = reinterpret_cast<const float4*>(inp)[row * 32 + lane];
    float4 w0 = reinterpret_cast<const float4*>(G0)[lane];
    float4 w1 = reinterpret_cast<const float4*>(G1)[lane];
    float4 w2 = reinterpret_cast<const float4*>(G2)[lane];
    float4 w3 = reinterpret_cast<const float4*>(G3)[lane];
    float d0 = v.x * w0.x + v.y * w0.y + v.z * w0.z + v.w * w0.w;
    float d1 = v.x * w1.x + v.y * w1.y + v.z * w1.z + v.w * w1.w;
    float d2 = v.x * w2.x + v.y * w2.y + v.z * w2.z + v.w * w2.w;
    float d3 = v.x * w3.x + v.y * w3.y + v.z * w3.z + v.w * w3.w;
    #pragma unroll
    for (int off = 16; off; off >>= 1) {
        d0 += __shfl_xor_sync(0xffffffff, d0, off);
        d1 += __shfl_xor_sync(0xffffffff, d1, off);
        d2 += __shfl_xor_sync(0xffffffff, d2, off);
        d3 += __shfl_xor_sync(0xffffffff, d3, off);
    }
    if (lane == 0) {
        g_G[0 * N_NODES + row] = d0;
        g_G[1 * N_NODES + row] = d1;
        g_G[2 * N_NODES + row] = d2;
        g_G[3 * N_NODES + row] = d3;
    }
}

// ---- gather: warp per target; 8-edge prefetch (MLP=8); inp reads hit L2 ----
// Accumulates H_t[tgt] = sum gate*inp[src] per type (regs), bias part -> out.
__global__ __launch_bounds__(256) void gather_kernel(
    const int* __restrict__ deprel, const int* __restrict__ deparc,
    const int* __restrict__ eidx, const float* __restrict__ inp,
    const float* __restrict__ b_in, const float* __restrict__ b_out,
    const float* __restrict__ bg_in, const float* __restrict__ bg_out,
    float* __restrict__ out)
{
    int n = (int)((blockIdx.x * blockDim.x + threadIdx.x) >> 5);
    if (n >= N_NODES) return;
    int lane = threadIdx.x & 31;

    int beg = g_start[n];
    int deg = g_cnt[n];
    float4 h0 = make_float4(0.f,0.f,0.f,0.f), h1 = h0, h2 = h0, h3 = h0, ab = h0;
    const float4* in4 = reinterpret_cast<const float4*>(inp);
    const float4* bi4 = reinterpret_cast<const float4*>(b_in);
    const float4* bo4 = reinterpret_cast<const float4*>(b_out);

    for (int base = 0; base < deg; base += 8) {
        int m = deg - base; if (m > 8) m = 8;
        int t = 0, rel = 0, src = 0;
        float gv = 0.f;
        if (lane < m) {
            int e = g_perm[beg + base + lane];
            t   = __ldg(&deparc[e]);
            rel = __ldg(&deprel[e]);
            src = __ldg(&eidx[e]);
            float gp = g_G[t * N_NODES + src];
            if (t == 0)      gp += __ldg(&bg_in[rel]);
            else if (t == 1) gp += __ldg(&bg_out[rel]);
            gv = 1.f / (1.f + __expf(-gp));
        }
        // broadcast metadata + issue all loads first (MLP=m)
        int   ti[8], ri[8];
        float gi[8];
        float4 v[8];
        #pragma unroll
        for (int i = 0; i < 8; i++) {
            if (i < m) {
                ti[i] = __shfl_sync(0xffffffff, t,   i);
                ri[i] = __shfl_sync(0xffffffff, rel, i);
                gi[i] = __shfl_sync(0xffffffff, gv,  i);
                int si = __shfl_sync(0xffffffff, src, i);
                v[i]  = in4[(size_t)si * 32 + lane];
            }
        }
        #pragma unroll
        for (int i = 0; i < 8; i++) {
            if (i < m) {
                float g = gi[i];
                float4 w = v[i];
                if (ti[i] == 0) {
                    h0.x += g * w.x; h0.y += g * w.y; h0.z += g * w.z; h0.w += g * w.w;
                    float4 b = bi4[ri[i] * 32 + lane];
                    ab.x += g * b.x; ab.y += g * b.y; ab.z += g * b.z; ab.w += g * b.w;
                } else if (ti[i] == 1) {
                    h1.x += g * w.x; h1.y += g * w.y; h1.z += g * w.z; h1.w += g * w.w;
                    float4 b = bo4[ri[i] * 32 + lane];
                    ab.x += g * b.x; ab.y += g * b.y; ab.z += g * b.z; ab.w += g * b.w;
                } else if (ti[i] == 2) {
                    h2.x += g * w.x; h2.y += g * w.y; h2.z += g * w.z; h2.w += g * w.w;
                } else {
                    h3.x += g * w.x; h3.y += g * w.y; h3.z += g * w.z; h3.w += g * w.w;
                }
            }
        }
    }

    // store H (fp16) and bias part (fp32 -> out)
    float4 hs[4] = {h0, h1, h2, h3};
    #pragma unroll
    for (int t = 0; t < 4; t++) {
        __half2 a = __float22half2_rn(make_float2(hs[t].x, hs[t].y));
        __half2 b = __float22half2_rn(make_float2(hs[t].z, hs[t].w));
        uint2 pk = make_uint2(*(uint32_t*)&a, *(uint32_t*)&b);
        *reinterpret_cast<uint2*>(&g_Hh[((size_t)t * N_PAD + n) * DMODEL + lane * 4]) = pk;
    }
    reinterpret_cast<float4*>(out)[(size_t)n * 32 + lane] = ab;
}

// ---- GEMM: out += sum_t H_t @ W_t^T ; 512 threads, double-buffered A and W ----
#define SM_A0  0
#define SM_A1  34816
#define SM_W0  69632
#define SM_W1  104448
#define SM_TOT 139264

__global__ __launch_bounds__(512, 1) void gemm_kernel(float* __restrict__ out)
{
    extern __shared__ char sm[];
    const uint32_t sBase = smem_u32(sm);
    const int tid  = threadIdx.x;
    const int warp = tid >> 5, lane = tid & 31;
    const int gid  = lane >> 2, tg = lane & 3;
    const int m0   = blockIdx.x * 128;
    const int lrow = tid & 127;
    const int lch0 = tid >> 7;              // 0..3

    // Issue H_0 tile (16 chunks/row) + W_0 tile (17 chunks/row)
    for (int ch = lch0; ch < 16; ch += 4)
        cpa16(sBase + SM_A0 + lrow * 272 + ch * 16,
              g_Hh + ((size_t)(m0 + lrow) * DMODEL + ch * 8));
    for (int ch = lch0; ch < 17; ch += 4)
        cpa16(sBase + SM_W0 + lrow * 272 + ch * 16, g_Wh4 + (lrow * 136 + ch * 8));
    CPA_COMMIT();

    const int mrow = (warp >> 1) * 16;
    const int nc0  = (warp & 1) * 64;

    float acc[8][4];
    #pragma unroll
    for (int j = 0; j < 8; j++) { acc[j][0] = acc[j][1] = acc[j][2] = acc[j][3] = 0.f; }

    #pragma unroll
    for (int t = 0; t < 4; t++) {
        CPA_WAIT0();
        __syncthreads();

        if (t < 3) {
            uint32_t dA = sBase + (((t + 1) & 1) ? SM_A1 : SM_A0);
            uint32_t dW = sBase + (((t + 1) & 1) ? SM_W1 : SM_W0);
            const __half* srcA = g_Hh + (size_t)(t + 1) * N_PAD * DMODEL;
            const __half* srcW = g_Wh4 + (t + 1) * 128 * 136;
            for (int ch = lch0; ch < 16; ch += 4)
                cpa16(dA + lrow * 272 + ch * 16,
                      srcA + ((size_t)(m0 + lrow) * DMODEL + ch * 8));
            for (int ch = lch0; ch < 17; ch += 4)
                cpa16(dW + lrow * 272 + ch * 16, srcW + (lrow * 136 + ch * 8));
            CPA_COMMIT();
        }

        const __half* Ah = (const __half*)(sm + ((t & 1) ? SM_A1 : SM_A0));
        const __half* Wh = (const __half*)(sm + ((t & 1) ? SM_W1 : SM_W0));

        #pragma unroll
        for (int k0 = 0; k0 < 128; k0 += 16) {
            unsigned a0 = *(const unsigned*)&Ah[(mrow + gid)     * 136 + k0 + 2 * tg];
            unsigned a1 = *(const unsigned*)&Ah[(mrow + gid + 8) * 136 + k0 + 2 * tg];
            unsigned a2 = *(const unsigned*)&Ah[(mrow + gid)     * 136 + k0 + 2 * tg + 8];
            unsigned a3 = *(const unsigned*)&Ah[(mrow + gid + 8) * 136 + k0 + 2 * tg + 8];
            #pragma unroll
            for (int j = 0; j < 8; j++) {
                unsigned b0 = *(const unsigned*)&Wh[(nc0 + j * 8 + gid) * 136 + k0 + 2 * tg];
                unsigned b1 = *(const unsigned*)&Wh[(nc0 + j * 8 + gid) * 136 + k0 + 2 * tg + 8];
                MMA_F16(acc[j], a0, a1, a2, a3, b0, b1);
            }
        }
        __syncthreads();
    }

    // Epilogue: out += acc (bias part already in out from gather)
    int r0 = m0 + mrow + gid, r1 = r0 + 8;
    #pragma unroll
    for (int j = 0; j < 8; j++) {
        int col = nc0 + j * 8 + 2 * tg;
        if (r0 < N_NODES) {
            float2* p = reinterpret_cast<float2*>(&out[(size_t)r0 * DMODEL + col]);
            float2 o = *p;
            *p = make_float2(o.x + acc[j][0], o.y + acc[j][1]);
        }
        if (r1 < N_NODES) {
            float2* p = reinterpret_cast<float2*>(&out[(size_t)r1 * DMODEL + col]);
            float2 o = *p;
            *p = make_float2(o.x + acc[j][2], o.y + acc[j][3]);
        }
    }
}

extern "C" void kernel_launch(void* const* d_in, const int* in_sizes, int n_in,
                              void* d_out, int out_size)
{
    const float* inp       = (const float*)d_in[0];
    const int*   deprel    = (const int*)d_in[1];
    const int*   deparc    = (const int*)d_in[2];
    const int*   eidx      = (const int*)d_in[3];
    const float* V_in      = (const float*)d_in[4];
    const float* b_in      = (const float*)d_in[5];
    const float* V_in_g    = (const float*)d_in[6];
    const float* b_in_g    = (const float*)d_in[7];
    const float* V_out     = (const float*)d_in[8];
    const float* b_out     = (const float*)d_in[9];
    const float* V_out_g   = (const float*)d_in[10];
    const float* b_out_g   = (const float*)d_in[11];
    const float* W_self    = (const float*)d_in[12];
    const float* W_self_g  = (const float*)d_in[13];
    const float* W_norel   = (const float*)d_in[14];
    const float* W_norel_g = (const float*)d_in[15];
    float* out = (float*)d_out;

    cudaFuncSetAttribute(gemm_kernel,
                         cudaFuncAttributeMaxDynamicSharedMemorySize, SM_TOT);

    // CSR build
    zero_kernel<<<(N_NODES + 255) / 256, 256>>>();
    hist_kernel<<<(N_EDGES + 255) / 256, 256>>>(eidx);
    alloc_kernel<<<(N_NODES + 255) / 256, 256>>>();
    scatter_kernel<<<(N_EDGES + 255) / 256, 256>>>(eidx);

    prep_weights_kernel<<<16, 256>>>(V_in, V_out, W_self, W_norel);
    gate_kernel<<<(N_NODES + 7) / 8, 256>>>(inp, V_in_g, V_out_g, W_self_g, W_norel_g);

    gather_kernel<<<(N_NODES * 32 + 255) / 256, 256>>>(
        deprel, deparc, eidx, inp, b_in, b_out, b_in_g, b_out_g, out);

    gemm_kernel<<<N_PAD / 128, 512, SM_TOT>>>(out);
}

// round 16
// speedup vs baseline: 1.7314x; 1.7314x over previous
#include <cuda_runtime.h>
#include <cuda_fp16.h>
#include <cstdint>
#include <cstddef>

#define N_NODES 100000
#define N_EDGES 600000
#define DMODEL  128
#define NREL    50
#define N_PAD   100096          // 782 tiles * 128

// Scratch
__device__ float  g_T[(size_t)4 * N_NODES * DMODEL];   // transformed features [4][N][128]
__device__ float  g_G[4 * N_NODES];                    // gate pre-activations
__device__ __half g_inph[(size_t)N_PAD * DMODEL];      // fp16 input copy (padded rows)
__device__ __half g_Wh4[4 * 128 * 136];                // fp16 weights, padded pitch 136

#define MMA_F16(c, a0, a1, a2, a3, b0, b1)                                   \
    asm volatile("mma.sync.aligned.m16n8k16.row.col.f32.f16.f16.f32 "        \
                 "{%0,%1,%2,%3}, {%4,%5,%6,%7}, {%8,%9}, {%0,%1,%2,%3};"     \
                 : "+f"(c[0]), "+f"(c[1]), "+f"(c[2]), "+f"(c[3])            \
                 : "r"(a0), "r"(a1), "r"(a2), "r"(a3), "r"(b0), "r"(b1))

__device__ __forceinline__ uint32_t smem_u32(const void* p) {
    uint32_t a;
    asm("{ .reg .u64 t; cvta.to.shared.u64 t, %1; cvt.u32.u64 %0, t; }" : "=r"(a) : "l"(p));
    return a;
}
__device__ __forceinline__ void cpa16(uint32_t dst, const void* src) {
    asm volatile("cp.async.cg.shared.global [%0], [%1], 16;" :: "r"(dst), "l"(src));
}
#define CPA_COMMIT() asm volatile("cp.async.commit_group;" ::: "memory")
#define CPA_WAIT0()  asm volatile("cp.async.wait_group 0;" ::: "memory")

// ---- prep 1: gate dots (fp32) + fp16 input copy + zero out[] (one pass) ----
__global__ __launch_bounds__(256) void prep_nodes_kernel(
    const float* __restrict__ inp,
    const float* __restrict__ G0, const float* __restrict__ G1,
    const float* __restrict__ G2, const float* __restrict__ G3,
    float* __restrict__ out)
{
    int warp = threadIdx.x >> 5, lane = threadIdx.x & 31;
    int row = blockIdx.x * 8 + warp;
    if (row >= N_NODES) return;

    float4 v  = reinterpret_cast<const float4*>(inp)[row * 32 + lane];
    float4 w0 = reinterpret_cast<const float4*>(G0)[lane];
    float4 w1 = reinterpret_cast<const float4*>(G1)[lane];
    float4 w2 = reinterpret_cast<const float4*>(G2)[lane];
    float4 w3 = reinterpret_cast<const float4*>(G3)[lane];
    float d0 = v.x * w0.x + v.y * w0.y + v.z * w0.z + v.w * w0.w;
    float d1 = v.x * w1.x + v.y * w1.y + v.z * w1.z + v.w * w1.w;
    float d2 = v.x * w2.x + v.y * w2.y + v.z * w2.z + v.w * w2.w;
    float d3 = v.x * w3.x + v.y * w3.y + v.z * w3.z + v.w * w3.w;
    #pragma unroll
    for (int off = 16; off; off >>= 1) {
        d0 += __shfl_xor_sync(0xffffffff, d0, off);
        d1 += __shfl_xor_sync(0xffffffff, d1, off);
        d2 += __shfl_xor_sync(0xffffffff, d2, off);
        d3 += __shfl_xor_sync(0xffffffff, d3, off);
    }
    if (lane == 0) {
        g_G[0 * N_NODES + row] = d0;
        g_G[1 * N_NODES + row] = d1;
        g_G[2 * N_NODES + row] = d2;
        g_G[3 * N_NODES + row] = d3;
    }
    __half2 h0 = __float22half2_rn(make_float2(v.x, v.y));
    __half2 h1 = __float22half2_rn(make_float2(v.z, v.w));
    uint2 pk = make_uint2(*(uint32_t*)&h0, *(uint32_t*)&h1);
    *reinterpret_cast<uint2*>(&g_inph[(size_t)row * DMODEL + lane * 4]) = pk;

    // zero the output row (replaces the separate memset launch)
    reinterpret_cast<float4*>(out)[(size_t)row * 32 + lane] =
        make_float4(0.f, 0.f, 0.f, 0.f);
}

// ---- prep 2: weights -> fp16, padded pitch-136 layout ----
__global__ __launch_bounds__(256) void prep_weights_kernel(
    const float* __restrict__ W0, const float* __restrict__ W1,
    const float* __restrict__ W2, const float* __restrict__ W3)
{
    for (int e = blockIdx.x * 256 + threadIdx.x; e < 4 * 128 * 64; e += gridDim.x * 256) {
        int t = e >> 13, r = (e >> 6) & 127, cp = e & 63;
        const float* W = (t == 0) ? W0 : (t == 1) ? W1 : (t == 2) ? W2 : W3;
        float2 v = reinterpret_cast<const float2*>(W)[r * 64 + cp];
        __half2 h = __float22half2_rn(v);
        *reinterpret_cast<__half2*>(&g_Wh4[t * 128 * 136 + r * 136 + 2 * cp]) = h;
    }
}

// ---- transform: 512 threads, cp.async double-buffered weights (R9-proven) ----
__global__ __launch_bounds__(512, 1) void transform_kernel()
{
    extern __shared__ char sm[];
    __half* Ah  = (__half*)sm;                     // [128][136]
    __half* Wb0 = (__half*)(sm + 34816);
    __half* Wb1 = (__half*)(sm + 69632);
    const uint32_t sA  = smem_u32(Ah);
    const uint32_t sW0 = smem_u32(Wb0);
    const uint32_t sW1 = smem_u32(Wb1);

    const int tid  = threadIdx.x;
    const int warp = tid >> 5, lane = tid & 31;
    const int gid  = lane >> 2, tg = lane & 3;
    const int m0   = blockIdx.x * 128;
    const int lrow = tid & 127;             // loader row
    const int lch0 = tid >> 7;              // loader chunk start (0..3)

    // Issue A tile + W[0] tile
    for (int ch = lch0; ch < 16; ch += 4)
        cpa16(sA + lrow * 272 + ch * 16, g_inph + ((size_t)(m0 + lrow) * DMODEL + ch * 8));
    for (int ch = lch0; ch < 17; ch += 4)
        cpa16(sW0 + lrow * 272 + ch * 16, g_Wh4 + (lrow * 136 + ch * 8));
    CPA_COMMIT();
    CPA_WAIT0();
    __syncthreads();

    const int mrow = (warp >> 1) * 16;
    const int nc0  = (warp & 1) * 64;

    #pragma unroll
    for (int t = 0; t < 4; t++) {
        // Prefetch next weight tile into the other buffer (overlaps with MMA below)
        if (t < 3) {
            uint32_t dstW = ((t + 1) & 1) ? sW1 : sW0;
            const __half* srcW = g_Wh4 + (t + 1) * 128 * 136;
            for (int ch = lch0; ch < 17; ch += 4)
                cpa16(dstW + lrow * 272 + ch * 16, srcW + (lrow * 136 + ch * 8));
            CPA_COMMIT();
        }

        const __half* Wh = (t & 1) ? Wb1 : Wb0;
        float acc[8][4];
        #pragma unroll
        for (int j = 0; j < 8; j++) { acc[j][0] = acc[j][1] = acc[j][2] = acc[j][3] = 0.f; }

        #pragma unroll
        for (int k0 = 0; k0 < 128; k0 += 16) {
            unsigned a0 = *(const unsigned*)&Ah[(mrow + gid)     * 136 + k0 + 2 * tg];
            unsigned a1 = *(const unsigned*)&Ah[(mrow + gid + 8) * 136 + k0 + 2 * tg];
            unsigned a2 = *(const unsigned*)&Ah[(mrow + gid)     * 136 + k0 + 2 * tg + 8];
            unsigned a3 = *(const unsigned*)&Ah[(mrow + gid + 8) * 136 + k0 + 2 * tg + 8];
            #pragma unroll
            for (int j = 0; j < 8; j++) {
                unsigned b0 = *(const unsigned*)&Wh[(nc0 + j * 8 + gid) * 136 + k0 + 2 * tg];
                unsigned b1 = *(const unsigned*)&Wh[(nc0 + j * 8 + gid) * 136 + k0 + 2 * tg + 8];
                MMA_F16(acc[j], a0, a1, a2, a3, b0, b1);
            }
        }

        float* Tout = g_T + (size_t)t * N_NODES * DMODEL;
        int r0 = m0 + mrow + gid, r1 = r0 + 8;
        #pragma unroll
        for (int j = 0; j < 8; j++) {
            int col = nc0 + j * 8 + 2 * tg;
            if (r0 < N_NODES)
                *reinterpret_cast<float2*>(&Tout[(size_t)r0 * DMODEL + col]) =
                    make_float2(acc[j][0], acc[j][1]);
            if (r1 < N_NODES)
                *reinterpret_cast<float2*>(&Tout[(size_t)r1 * DMODEL + col]) =
                    make_float2(acc[j][2], acc[j][3]);
        }

        CPA_WAIT0();
        __syncthreads();
    }
}

// ---- edge phase: 4 edges per warp, batched loads, red.global.add.v4 ----
#define EDGES_PER_WARP 4
__global__ __launch_bounds__(256) void edge_kernel(
    const int* __restrict__ deprel, const int* __restrict__ deparc,
    const int* __restrict__ eidx,
    const float* __restrict__ b_in, const float* __restrict__ b_out,
    const float* __restrict__ bg_in, const float* __restrict__ bg_out,
    float* __restrict__ out)
{
    int w = (int)((blockIdx.x * blockDim.x + threadIdx.x) >> 5);
    int lane = threadIdx.x & 31;
    int e0 = w * EDGES_PER_WARP;

    int   t[EDGES_PER_WARP], rel[EDGES_PER_WARP], tgt[EDGES_PER_WARP];
    float4 v[EDGES_PER_WARP];
    float  gpre[EDGES_PER_WARP];
    bool   ok[EDGES_PER_WARP];

    // Pass 1: indices (4 independent load groups)
    #pragma unroll
    for (int q = 0; q < EDGES_PER_WARP; q++) {
        int e = e0 + q;
        ok[q] = (e < N_EDGES);
        int ec = ok[q] ? e : (N_EDGES - 1);
        t[q]   = __ldg(&deparc[ec]);
        rel[q] = __ldg(&deprel[ec]);
        tgt[q] = __ldg(&eidx[N_EDGES + ec]);
    }
    // Pass 2: feature-row + gate loads (4 independent 16B loads in flight)
    #pragma unroll
    for (int q = 0; q < EDGES_PER_WARP; q++) {
        int e = e0 + q;
        int ec = ok[q] ? e : (N_EDGES - 1);
        int src = __ldg(&eidx[ec]);
        const float* trow = g_T + ((size_t)t[q] * N_NODES + src) * DMODEL;
        v[q] = reinterpret_cast<const float4*>(trow)[lane];
        gpre[q] = g_G[t[q] * N_NODES + src];
    }
    // Pass 3: bias, gate, reduce
    #pragma unroll
    for (int q = 0; q < EDGES_PER_WARP; q++) {
        if (!ok[q]) continue;
        float4 b = make_float4(0.f, 0.f, 0.f, 0.f);
        if (t[q] == 0) {
            b = reinterpret_cast<const float4*>(b_in)[rel[q] * 32 + lane];
            gpre[q] += __ldg(&bg_in[rel[q]]);
        } else if (t[q] == 1) {
            b = reinterpret_cast<const float4*>(b_out)[rel[q] * 32 + lane];
            gpre[q] += __ldg(&bg_out[rel[q]]);
        }
        float g = 1.f / (1.f + __expf(-gpre[q]));
        float4 r;
        r.x = (v[q].x + b.x) * g;
        r.y = (v[q].y + b.y) * g;
        r.z = (v[q].z + b.z) * g;
        r.w = (v[q].w + b.w) * g;
        float* dst = out + (size_t)tgt[q] * DMODEL + lane * 4;
        asm volatile("red.global.add.v4.f32 [%0], {%1,%2,%3,%4};"
                     :: "l"(dst), "f"(r.x), "f"(r.y), "f"(r.z), "f"(r.w)
                     : "memory");
    }
}

extern "C" void kernel_launch(void* const* d_in, const int* in_sizes, int n_in,
                              void* d_out, int out_size)
{
    const float* inp       = (const float*)d_in[0];
    const int*   deprel    = (const int*)d_in[1];
    const int*   deparc    = (const int*)d_in[2];
    const int*   eidx      = (const int*)d_in[3];
    const float* V_in      = (const float*)d_in[4];
    const float* b_in      = (const float*)d_in[5];
    const float* V_in_g    = (const float*)d_in[6];
    const float* b_in_g    = (const float*)d_in[7];
    const float* V_out     = (const float*)d_in[8];
    const float* b_out     = (const float*)d_in[9];
    const float* V_out_g   = (const float*)d_in[10];
    const float* b_out_g   = (const float*)d_in[11];
    const float* W_self    = (const float*)d_in[12];
    const float* W_self_g  = (const float*)d_in[13];
    const float* W_norel   = (const float*)d_in[14];
    const float* W_norel_g = (const float*)d_in[15];
    float* out = (float*)d_out;

    const int smem = 34816 * 3;   // Ah + 2x W buffers = 104448 B
    cudaFuncSetAttribute(transform_kernel,
                         cudaFuncAttributeMaxDynamicSharedMemorySize, smem);

    prep_weights_kernel<<<16, 256>>>(V_in, V_out, W_self, W_norel);
    prep_nodes_kernel<<<(N_NODES + 7) / 8, 256>>>(
        inp, V_in_g, V_out_g, W_self_g, W_norel_g, out);

    transform_kernel<<<N_PAD / 128, 512, smem>>>();

    const int warps_needed = (N_EDGES + EDGES_PER_WARP - 1) / EDGES_PER_WARP;
    edge_kernel<<<(warps_needed * 32 + 255) / 256, 256>>>(
        deprel, deparc, eidx, b_in, b_out, b_in_g, b_out_g, out);
}

// round 17
// speedup vs baseline: 1.8236x; 1.0532x over previous
#include <cuda_runtime.h>
#include <cuda_fp16.h>
#include <cstdint>
#include <cstddef>

#define N_NODES 100000
#define N_EDGES 600000
#define DMODEL  128
#define NREL    50
#define N_PAD   100096          // 782 tiles * 128

// Scratch
__device__ __half g_T[(size_t)4 * N_NODES * DMODEL];   // transformed features, fp16 (102.5 MB, L2-resident)
__device__ float  g_G[4 * N_NODES];                    // gate pre-activations
__device__ __half g_inph[(size_t)N_PAD * DMODEL];      // fp16 input copy (padded rows)
__device__ __half g_Wh4[4 * 128 * 136];                // fp16 weights, padded pitch 136

#define MMA_F16(c, a0, a1, a2, a3, b0, b1)                                   \
    asm volatile("mma.sync.aligned.m16n8k16.row.col.f32.f16.f16.f32 "        \
                 "{%0,%1,%2,%3}, {%4,%5,%6,%7}, {%8,%9}, {%0,%1,%2,%3};"     \
                 : "+f"(c[0]), "+f"(c[1]), "+f"(c[2]), "+f"(c[3])            \
                 : "r"(a0), "r"(a1), "r"(a2), "r"(a3), "r"(b0), "r"(b1))

__device__ __forceinline__ uint32_t smem_u32(const void* p) {
    uint32_t a;
    asm("{ .reg .u64 t; cvta.to.shared.u64 t, %1; cvt.u32.u64 %0, t; }" : "=r"(a) : "l"(p));
    return a;
}
__device__ __forceinline__ void cpa16(uint32_t dst, const void* src) {
    asm volatile("cp.async.cg.shared.global [%0], [%1], 16;" :: "r"(dst), "l"(src));
}
#define CPA_COMMIT() asm volatile("cp.async.commit_group;" ::: "memory")
#define CPA_WAIT0()  asm volatile("cp.async.wait_group 0;" ::: "memory")

// ---- prep 1: gate dots (fp32) + fp16 input copy + zero out[] (one pass) ----
__global__ __launch_bounds__(256) void prep_nodes_kernel(
    const float* __restrict__ inp,
    const float* __restrict__ G0, const float* __restrict__ G1,
    const float* __restrict__ G2, const float* __restrict__ G3,
    float* __restrict__ out)
{
    int warp = threadIdx.x >> 5, lane = threadIdx.x & 31;
    int row = blockIdx.x * 8 + warp;
    if (row >= N_NODES) return;

    float4 v  = reinterpret_cast<const float4*>(inp)[row * 32 + lane];
    float4 w0 = reinterpret_cast<const float4*>(G0)[lane];
    float4 w1 = reinterpret_cast<const float4*>(G1)[lane];
    float4 w2 = reinterpret_cast<const float4*>(G2)[lane];
    float4 w3 = reinterpret_cast<const float4*>(G3)[lane];
    float d0 = v.x * w0.x + v.y * w0.y + v.z * w0.z + v.w * w0.w;
    float d1 = v.x * w1.x + v.y * w1.y + v.z * w1.z + v.w * w1.w;
    float d2 = v.x * w2.x + v.y * w2.y + v.z * w2.z + v.w * w2.w;
    float d3 = v.x * w3.x + v.y * w3.y + v.z * w3.z + v.w * w3.w;
    #pragma unroll
    for (int off = 16; off; off >>= 1) {
        d0 += __shfl_xor_sync(0xffffffff, d0, off);
        d1 += __shfl_xor_sync(0xffffffff, d1, off);
        d2 += __shfl_xor_sync(0xffffffff, d2, off);
        d3 += __shfl_xor_sync(0xffffffff, d3, off);
    }
    if (lane == 0) {
        g_G[0 * N_NODES + row] = d0;
        g_G[1 * N_NODES + row] = d1;
        g_G[2 * N_NODES + row] = d2;
        g_G[3 * N_NODES + row] = d3;
    }
    __half2 h0 = __float22half2_rn(make_float2(v.x, v.y));
    __half2 h1 = __float22half2_rn(make_float2(v.z, v.w));
    uint2 pk = make_uint2(*(uint32_t*)&h0, *(uint32_t*)&h1);
    *reinterpret_cast<uint2*>(&g_inph[(size_t)row * DMODEL + lane * 4]) = pk;

    // zero the output row (replaces the separate memset launch)
    reinterpret_cast<float4*>(out)[(size_t)row * 32 + lane] =
        make_float4(0.f, 0.f, 0.f, 0.f);
}

// ---- prep 2: weights -> fp16, padded pitch-136 layout ----
__global__ __launch_bounds__(256) void prep_weights_kernel(
    const float* __restrict__ W0, const float* __restrict__ W1,
    const float* __restrict__ W2, const float* __restrict__ W3)
{
    for (int e = blockIdx.x * 256 + threadIdx.x; e < 4 * 128 * 64; e += gridDim.x * 256) {
        int t = e >> 13, r = (e >> 6) & 127, cp = e & 63;
        const float* W = (t == 0) ? W0 : (t == 1) ? W1 : (t == 2) ? W2 : W3;
        float2 v = reinterpret_cast<const float2*>(W)[r * 64 + cp];
        __half2 h = __float22half2_rn(v);
        *reinterpret_cast<__half2*>(&g_Wh4[t * 128 * 136 + r * 136 + 2 * cp]) = h;
    }
}

// ---- transform: 512 threads, cp.async double-buffered weights; fp16 output ----
__global__ __launch_bounds__(512, 1) void transform_kernel()
{
    extern __shared__ char sm[];
    __half* Ah  = (__half*)sm;                     // [128][136]
    __half* Wb0 = (__half*)(sm + 34816);
    __half* Wb1 = (__half*)(sm + 69632);
    const uint32_t sA  = smem_u32(Ah);
    const uint32_t sW0 = smem_u32(Wb0);
    const uint32_t sW1 = smem_u32(Wb1);

    const int tid  = threadIdx.x;
    const int warp = tid >> 5, lane = tid & 31;
    const int gid  = lane >> 2, tg = lane & 3;
    const int m0   = blockIdx.x * 128;
    const int lrow = tid & 127;             // loader row
    const int lch0 = tid >> 7;              // loader chunk start (0..3)

    // Issue A tile + W[0] tile
    for (int ch = lch0; ch < 16; ch += 4)
        cpa16(sA + lrow * 272 + ch * 16, g_inph + ((size_t)(m0 + lrow) * DMODEL + ch * 8));
    for (int ch = lch0; ch < 17; ch += 4)
        cpa16(sW0 + lrow * 272 + ch * 16, g_Wh4 + (lrow * 136 + ch * 8));
    CPA_COMMIT();
    CPA_WAIT0();
    __syncthreads();

    const int mrow = (warp >> 1) * 16;
    const int nc0  = (warp & 1) * 64;

    #pragma unroll
    for (int t = 0; t < 4; t++) {
        // Prefetch next weight tile into the other buffer (overlaps with MMA below)
        if (t < 3) {
            uint32_t dstW = ((t + 1) & 1) ? sW1 : sW0;
            const __half* srcW = g_Wh4 + (t + 1) * 128 * 136;
            for (int ch = lch0; ch < 17; ch += 4)
                cpa16(dstW + lrow * 272 + ch * 16, srcW + (lrow * 136 + ch * 8));
            CPA_COMMIT();
        }

        const __half* Wh = (t & 1) ? Wb1 : Wb0;
        float acc[8][4];
        #pragma unroll
        for (int j = 0; j < 8; j++) { acc[j][0] = acc[j][1] = acc[j][2] = acc[j][3] = 0.f; }

        #pragma unroll
        for (int k0 = 0; k0 < 128; k0 += 16) {
            unsigned a0 = *(const unsigned*)&Ah[(mrow + gid)     * 136 + k0 + 2 * tg];
            unsigned a1 = *(const unsigned*)&Ah[(mrow + gid + 8) * 136 + k0 + 2 * tg];
            unsigned a2 = *(const unsigned*)&Ah[(mrow + gid)     * 136 + k0 + 2 * tg + 8];
            unsigned a3 = *(const unsigned*)&Ah[(mrow + gid + 8) * 136 + k0 + 2 * tg + 8];
            #pragma unroll
            for (int j = 0; j < 8; j++) {
                unsigned b0 = *(const unsigned*)&Wh[(nc0 + j * 8 + gid) * 136 + k0 + 2 * tg];
                unsigned b1 = *(const unsigned*)&Wh[(nc0 + j * 8 + gid) * 136 + k0 + 2 * tg + 8];
                MMA_F16(acc[j], a0, a1, a2, a3, b0, b1);
            }
        }

        // fp16 epilogue: 4B half2 stores
        __half* Tout = g_T + (size_t)t * N_NODES * DMODEL;
        int r0 = m0 + mrow + gid, r1 = r0 + 8;
        #pragma unroll
        for (int j = 0; j < 8; j++) {
            int col = nc0 + j * 8 + 2 * tg;
            if (r0 < N_NODES)
                *reinterpret_cast<__half2*>(&Tout[(size_t)r0 * DMODEL + col]) =
                    __float22half2_rn(make_float2(acc[j][0], acc[j][1]));
            if (r1 < N_NODES)
                *reinterpret_cast<__half2*>(&Tout[(size_t)r1 * DMODEL + col]) =
                    __float22half2_rn(make_float2(acc[j][2], acc[j][3]));
        }

        CPA_WAIT0();
        __syncthreads();
    }
}

// ---- edge phase: 4 edges per warp; fp16 T gather (8B/lane); red.global.add.v4 ----
#define EDGES_PER_WARP 4
__global__ __launch_bounds__(256) void edge_kernel(
    const int* __restrict__ deprel, const int* __restrict__ deparc,
    const int* __restrict__ eidx,
    const float* __restrict__ b_in, const float* __restrict__ b_out,
    const float* __restrict__ bg_in, const float* __restrict__ bg_out,
    float* __restrict__ out)
{
    int w = (int)((blockIdx.x * blockDim.x + threadIdx.x) >> 5);
    int lane = threadIdx.x & 31;
    int e0 = w * EDGES_PER_WARP;

    int   t[EDGES_PER_WARP], rel[EDGES_PER_WARP], tgt[EDGES_PER_WARP];
    uint2 vh[EDGES_PER_WARP];
    float gpre[EDGES_PER_WARP];
    bool  ok[EDGES_PER_WARP];

    // Pass 1: indices
    #pragma unroll
    for (int q = 0; q < EDGES_PER_WARP; q++) {
        int e = e0 + q;
        ok[q] = (e < N_EDGES);
        int ec = ok[q] ? e : (N_EDGES - 1);
        t[q]   = __ldg(&deparc[ec]);
        rel[q] = __ldg(&deprel[ec]);
        tgt[q] = __ldg(&eidx[N_EDGES + ec]);
    }
    // Pass 2: fp16 feature-row (8B/lane) + gate loads, 4 independent in flight
    #pragma unroll
    for (int q = 0; q < EDGES_PER_WARP; q++) {
        int e = e0 + q;
        int ec = ok[q] ? e : (N_EDGES - 1);
        int src = __ldg(&eidx[ec]);
        const __half* trow = g_T + ((size_t)t[q] * N_NODES + src) * DMODEL;
        vh[q] = *reinterpret_cast<const uint2*>(trow + lane * 4);
        gpre[q] = g_G[t[q] * N_NODES + src];
    }
    // Pass 3: bias, gate, reduce
    #pragma unroll
    for (int q = 0; q < EDGES_PER_WARP; q++) {
        if (!ok[q]) continue;
        float2 vlo = __half22float2(*reinterpret_cast<__half2*>(&vh[q].x));
        float2 vhi = __half22float2(*reinterpret_cast<__half2*>(&vh[q].y));
        float4 b = make_float4(0.f, 0.f, 0.f, 0.f);
        if (t[q] == 0) {
            b = reinterpret_cast<const float4*>(b_in)[rel[q] * 32 + lane];
            gpre[q] += __ldg(&bg_in[rel[q]]);
        } else if (t[q] == 1) {
            b = reinterpret_cast<const float4*>(b_out)[rel[q] * 32 + lane];
            gpre[q] += __ldg(&bg_out[rel[q]]);
        }
        float g = 1.f / (1.f + __expf(-gpre[q]));
        float4 r;
        r.x = (vlo.x + b.x) * g;
        r.y = (vlo.y + b.y) * g;
        r.z = (vhi.x + b.z) * g;
        r.w = (vhi.y + b.w) * g;
        float* dst = out + (size_t)tgt[q] * DMODEL + lane * 4;
        asm volatile("red.global.add.v4.f32 [%0], {%1,%2,%3,%4};"
                     :: "l"(dst), "f"(r.x), "f"(r.y), "f"(r.z), "f"(r.w)
                     : "memory");
    }
}

extern "C" void kernel_launch(void* const* d_in, const int* in_sizes, int n_in,
                              void* d_out, int out_size)
{
    const float* inp       = (const float*)d_in[0];
    const int*   deprel    = (const int*)d_in[1];
    const int*   deparc    = (const int*)d_in[2];
    const int*   eidx      = (const int*)d_in[3];
    const float* V_in      = (const float*)d_in[4];
    const float* b_in      = (const float*)d_in[5];
    const float* V_in_g    = (const float*)d_in[6];
    const float* b_in_g    = (const float*)d_in[7];
    const float* V_out     = (const float*)d_in[8];
    const float* b_out     = (const float*)d_in[9];
    const float* V_out_g   = (const float*)d_in[10];
    const float* b_out_g   = (const float*)d_in[11];
    const float* W_self    = (const float*)d_in[12];
    const float* W_self_g  = (const float*)d_in[13];
    const float* W_norel   = (const float*)d_in[14];
    const float* W_norel_g = (const float*)d_in[15];
    float* out = (float*)d_out;

    const int smem = 34816 * 3;   // Ah + 2x W buffers = 104448 B
    cudaFuncSetAttribute(transform_kernel,
                         cudaFuncAttributeMaxDynamicSharedMemorySize, smem);

    prep_weights_kernel<<<16, 256>>>(V_in, V_out, W_self, W_norel);
    prep_nodes_kernel<<<(N_NODES + 7) / 8, 256>>>(
        inp, V_in_g, V_out_g, W_self_g, W_norel_g, out);

    transform_kernel<<<N_PAD / 128, 512, smem>>>();

    const int warps_needed = (N_EDGES + EDGES_PER_WARP - 1) / EDGES_PER_WARP;
    edge_kernel<<<(warps_needed * 32 + 255) / 256, 256>>>(
        deprel, deparc, eidx, b_in, b_out, b_in_g, b_out_g, out);
}